// round 17
// baseline (speedup 1.0000x reference)
#include <cuda_runtime.h>

#define NBOX 4096
#define T 1024
#define PER 4                  // NBOX / T
#define NWARP 32
#define PROD (NWARP - 1)       // producer = HIGHEST wid (hi-wid-first arbiter)
#define BMAX 64
#define THRESH 0.05f
#define FULL 0xffffffffu

__device__ float4 g_sbox[NBOX];
__device__ int    g_orig[NBOX];

__global__ __launch_bounds__(T, 1)
void softnms_kernel(const float4* __restrict__ boxes,
                    const float*  __restrict__ scores,
                    float* __restrict__ out, int out_size)
{
    __shared__ unsigned long long skv[NBOX];   // sort scratch
    __shared__ uint4    spoolA[NWARP];         // (k1, p1, k2, p2) exact keys
    __shared__ unsigned sm3[NWARP];            // per-warp 3rd-best value
    __shared__ float4   sbatch_box[BMAX];
    __shared__ uint2    sbatch_meta[BMAX];     // (sorted pos, exact score bits)
    __shared__ int      sB, sfro, sfpos;

    const int t    = threadIdx.x;
    const int lane = t & 31;
    const int wid  = t >> 5;

    // ---- init: zero score outputs, stage u64 sort keys ----
#pragma unroll
    for (int k = 0; k < PER; k++) {
        const int gi = t * PER + k;
        if (gi < out_size) out[gi] = 0.0f;
        skv[gi] = ((unsigned long long)__float_as_uint(boxes[gi].x) << 32)
                  | (unsigned)gi;
    }
    __syncthreads();

    // ---- bitonic sort ascending by x1 ----
    for (int k = 2; k <= NBOX; k <<= 1) {
        for (int j = k >> 1; j > 0; j >>= 1) {
#pragma unroll
            for (int e = t; e < NBOX; e += T) {
                const int ixj = e ^ j;
                if (ixj > e) {
                    const unsigned long long a = skv[e], c = skv[ixj];
                    const bool up = ((e & k) == 0);
                    if (up ? (a > c) : (a < c)) { skv[e] = c; skv[ixj] = a; }
                }
            }
            __syncthreads();
        }
    }

    // ---- load my PER sorted boxes; publish sorted tables ----
    float x1[PER], y1[PER], x2[PER], y2[PER], area[PER], s[PER];
    int   orig[PER];
    unsigned procm = 0;
    float tx2hi = 0.0f;
#pragma unroll
    for (int k = 0; k < PER; k++) {
        const int pos = t * PER + k;
        const int o   = (int)(unsigned)(skv[pos] & 0xffffffffu);
        orig[k] = o;
        const float4 b = boxes[o];
        x1[k] = b.x; y1[k] = b.y; x2[k] = b.z; y2[k] = b.w;
        area[k] = (b.z - b.x) * (b.w - b.y);
        s[k]    = scores[o];
        g_sbox[pos] = b;
        g_orig[pos] = o;
        tx2hi = fmaxf(tx2hi, b.z);
    }
    const float tx1lo = x1[0];
    __syncthreads();

    bool dirty = true;
    int  step  = 0;
    int  fro_final = 0, fpos_final = 0;

    while (step < NBOX) {
        // ========= rebuild per-warp top-2 (+3rd value), EXACT argmax =======
        if (__ballot_sync(FULL, dirty)) {
            unsigned b1 = 0, b2 = 0, b3 = 0, p1 = 0, p2 = 0;
#pragma unroll
            for (int k = 0; k < PER; k++) {
                if (!((procm >> k) & 1u)) {
                    const unsigned ub = __float_as_uint(s[k]);   // scores > 0
                    const unsigned up = (unsigned)(t * PER + k);
                    if (ub > b1)      { b3 = b2; b2 = b1; p2 = p1; b1 = ub; p1 = up; }
                    else if (ub > b2) { b3 = b2; b2 = ub; p2 = up; }
                    else if (ub > b3) { b3 = ub; }
                }
            }
            const unsigned m1   = __reduce_max_sync(FULL, b1);
            const unsigned bal1 = __ballot_sync(FULL, b1 == m1);
            const int s1        = __ffs(bal1) - 1;
            const unsigned q1   = __shfl_sync(FULL, p1, s1);
            const unsigned v2   = (lane == s1) ? b2 : b1;
            const unsigned vp2  = (lane == s1) ? p2 : p1;
            const unsigned m2   = __reduce_max_sync(FULL, v2);
            const unsigned bal2 = __ballot_sync(FULL, v2 == m2);
            const int s2        = __ffs(bal2) - 1;
            const unsigned q2   = __shfl_sync(FULL, vp2, s2);
            unsigned v3 = b1;
            if (lane == s1) v3 = b2;
            if (lane == s2) v3 = (s2 == s1) ? b3 : b2;
            const unsigned m3 = __reduce_max_sync(FULL, v3);
            if (lane == 0) { spoolA[wid] = make_uint4(m1, q1, m2, q2); sm3[wid] = m3; }
            dirty = false;
        }
        __syncthreads();   // bar1: pools visible; consumers park in bar2 next

        if (wid == PROD) {
            // ==== producer: PIPELINED batch scan (decay lags one accept) ===
            const uint4 a = spoolA[lane];
            unsigned k1 = a.x, pp1 = a.y, k2 = a.z, pp2 = a.w;
            const unsigned M3 = __reduce_max_sync(FULL, sm3[lane]);
            const float4 f1 = g_sbox[pp1]; const float a1 = (f1.z - f1.x) * (f1.w - f1.y);
            const float4 f2 = g_sbox[pp2]; const float a2 = (f2.z - f2.x) * (f2.w - f2.y);
            const unsigned TB = __float_as_uint(THRESH);

            int B = 0, fz = 0; unsigned fp = 0;

            // initial selection (no pending decay)
            unsigned tmask = 0u;
            bool s1w      = (k1 >= k2);
            unsigned kmax = s1w ? k1 : k2;
            unsigned m    = __reduce_max_sync(FULL, kmax);
            unsigned bal  = __ballot_sync(FULL, kmax == m);

            while (true) {
                // ---- validate speculation: any stale-high lane claiming max?
                if (bal & tmask) {              // ~4%: redo on decayed keys
                    s1w  = (k1 >= k2);
                    kmax = s1w ? k1 : k2;
                    m    = __reduce_max_sync(FULL, kmax);
                    bal  = __ballot_sync(FULL, kmax == m);
                }
                if (m < M3) break;              // pool no longer covers order
                const int src = __ffs(bal) - 1;
                if (m <= TB) {                  // pool max == global max
                    fz = 1;
                    fp = __shfl_sync(FULL, s1w ? pp1 : pp2, src);
                    break;
                }
                const bool is_src = (lane == src);
                // member coords (off the selection chain)
                const float mx1 = __shfl_sync(FULL, s1w ? f1.x : f2.x, src);
                const float my1 = __shfl_sync(FULL, s1w ? f1.y : f2.y, src);
                const float mx2 = __shfl_sync(FULL, s1w ? f1.z : f2.z, src);
                const float my2 = __shfl_sync(FULL, s1w ? f1.w : f2.w, src);
                const float mar = (mx2 - mx1) * (my2 - my1);
                if (is_src) {                   // plain STS; bar2 publishes
                    sbatch_box[B]  = make_float4(mx1, my1, mx2, my2);
                    sbatch_meta[B] = make_uint2(s1w ? pp1 : pp2, m);
                }
                // consume winner slot BEFORE speculative next selection
                k1 = (is_src &&  s1w) ? 0u : k1;
                k2 = (is_src && !s1w) ? 0u : k2;
                B++;
                if (B >= BMAX) break;

                // ---- cheap overlap flags (feed tmask ballot, off chain) ----
                const float iw1 = fmaxf(fminf(mx2, f1.z) - fmaxf(mx1, f1.x), 0.0f);
                const float ih1 = fmaxf(fminf(my2, f1.w) - fmaxf(my1, f1.y), 0.0f);
                const float inter1 = iw1 * ih1;
                const float iw2 = fmaxf(fminf(mx2, f2.z) - fmaxf(mx1, f2.x), 0.0f);
                const float ih2 = fmaxf(fminf(my2, f2.w) - fmaxf(my1, f2.y), 0.0f);
                const float inter2 = iw2 * ih2;

                // ---- speculative next selection on PRE-decay keys ----
                const bool s1wN      = (k1 >= k2);
                const unsigned kmaxN = s1wN ? k1 : k2;
                const bool touched   = s1wN ? (inter1 > 0.0f) : (inter2 > 0.0f);
                const unsigned mN    = __reduce_max_sync(FULL, kmaxN);
                const unsigned tm    = __ballot_sync(FULL, touched);
                const unsigned balN  = __ballot_sync(FULL, kmaxN == mN);

                // ---- decay executes in the redux/ballot shadow (bit-exact;
                //      inter==0 -> *1.0f leaves key bits unchanged) ----
                {
                    const float iou = __fdividef(inter1, mar + a1 - inter1);
                    k1 = __float_as_uint(__uint_as_float(k1) * __expf(-2.0f * iou * iou));
                }
                {
                    const float iou = __fdividef(inter2, mar + a2 - inter2);
                    k2 = __float_as_uint(__uint_as_float(k2) * __expf(-2.0f * iou * iou));
                }
                // hand off to next round
                s1w = s1wN; kmax = kmaxN; m = mN; bal = balN; tmask = tm;
            }
            if (lane == 0) { sB = B; sfro = fz; sfpos = (int)fp; }
        }
        __syncthreads();   // bar2: batch + flags visible to everyone

        const int B = sB;

        // ---- parallel idxs writes: thread j handles member j ----
        if (t < B && (NBOX + step + t) < out_size)
            out[NBOX + step + t] = (float)g_orig[sbatch_meta[t].x];

        // ---- apply batch decay: my PER boxes vs all B members ----
        for (int j = 0; j < B; j++) {
            const float4 mb = sbatch_box[j];       // LDS broadcast
            if (mb.x <= tx2hi && mb.z >= tx1lo) {  // x-interval skip (exact)
                const uint2 mm  = sbatch_meta[j];
                const float mar = (mb.z - mb.x) * (mb.w - mb.y);
#pragma unroll
                for (int k = 0; k < PER; k++) {
                    if ((procm >> k) & 1u) continue;
                    if (t * PER + k == (int)mm.x) {
                        procm |= 1u << k;
                        if (orig[k] < out_size) out[orig[k]] = __uint_as_float(mm.y);
                        dirty = true;
                    } else {
                        const float iw = fmaxf(fminf(mb.z, x2[k]) - fmaxf(mb.x, x1[k]), 0.0f);
                        const float ih = fmaxf(fminf(mb.w, y2[k]) - fmaxf(mb.y, y1[k]), 0.0f);
                        const float inter = iw * ih;
                        if (inter > 0.0f) {
                            const float iou = __fdividef(inter, mar + area[k] - inter);
                            s[k] *= __expf(-2.0f * iou * iou);
                            dirty = true;
                        }
                    }
                }
            }
        }
        step += B;
        if (sfro) { fro_final = 1; fpos_final = sfpos; break; }
    }

    // ---- frozen tail: all remaining steps re-select the same argmax ----
    if (fro_final && step < NBOX) {
        const int fo = g_orig[fpos_final];
        for (int j = step + t; j < NBOX; j += T) {
            if ((NBOX + j) < out_size) out[NBOX + j] = (float)fo;
        }
    }
}

extern "C" void kernel_launch(void* const* d_in, const int* in_sizes, int n_in,
                              void* d_out, int out_size)
{
    const float4* boxes;
    const float*  scores;
    if (in_sizes[0] == 4 * NBOX) {
        boxes  = (const float4*)d_in[0];
        scores = (const float*)d_in[1];
    } else {
        boxes  = (const float4*)d_in[1];
        scores = (const float*)d_in[0];
    }
    softnms_kernel<<<1, T>>>(boxes, scores, (float*)d_out, out_size);
}